// round 1
// baseline (speedup 1.0000x reference)
#include <cuda_runtime.h>

#define BB 8
#define SS 1024
#define DD 1024
#define HH 16
#define DH 64

// Scratch (allocation-free rule: __device__ globals)
__device__ float g_qkv[(size_t)BB * SS * 3 * DD];   // [8,1024,3072]
__device__ float g_attn[(size_t)BB * SS * DD];      // [8,1024,1024]

// ---------------------------------------------------------------------------
// GEMM: C[M,N] = A[M,K] @ W[K,N], row-major fp32.
// 128x128x16 tiles, 256 threads, 8x8 per-thread microtile, register prefetch.
// ---------------------------------------------------------------------------
__global__ void __launch_bounds__(256, 2)
gemm_kernel(const float* __restrict__ A, const float* __restrict__ W,
            float* __restrict__ C, int M, int N, int K) {
    __shared__ float As[16][128 + 4];
    __shared__ float Bs[16][128];

    const int t = threadIdx.x;
    const int block_m = blockIdx.y * 128;
    const int block_n = blockIdx.x * 128;
    const int ty = t / 16;          // 0..15
    const int tx = t % 16;          // 0..15

    // A load mapping: 2 float4 per thread
    const int am = t / 4;           // 0..63 (and +64)
    const int ak = (t % 4) * 4;     // 0,4,8,12
    // B load mapping: 2 float4 per thread
    const int bk = t / 32;          // 0..7 (and +8)
    const int bn = (t % 32) * 4;    // 0..124

    const float* Ap = A + (size_t)block_m * K;
    const float* Wp = W + block_n;

    float acc[8][8];
#pragma unroll
    for (int i = 0; i < 8; i++)
#pragma unroll
        for (int j = 0; j < 8; j++) acc[i][j] = 0.f;

    // prefetch first tile
    float4 pa0 = *(const float4*)(Ap + (size_t)am * K + ak);
    float4 pa1 = *(const float4*)(Ap + (size_t)(am + 64) * K + ak);
    float4 pb0 = *(const float4*)(Wp + (size_t)bk * N + bn);
    float4 pb1 = *(const float4*)(Wp + (size_t)(bk + 8) * N + bn);

    for (int k0 = 0; k0 < K; k0 += 16) {
        // commit prefetched tile to smem (A transposed)
        As[ak + 0][am] = pa0.x; As[ak + 1][am] = pa0.y;
        As[ak + 2][am] = pa0.z; As[ak + 3][am] = pa0.w;
        As[ak + 0][am + 64] = pa1.x; As[ak + 1][am + 64] = pa1.y;
        As[ak + 2][am + 64] = pa1.z; As[ak + 3][am + 64] = pa1.w;
        *(float4*)&Bs[bk][bn] = pb0;
        *(float4*)&Bs[bk + 8][bn] = pb1;
        __syncthreads();

        if (k0 + 16 < K) {
            pa0 = *(const float4*)(Ap + (size_t)am * K + k0 + 16 + ak);
            pa1 = *(const float4*)(Ap + (size_t)(am + 64) * K + k0 + 16 + ak);
            pb0 = *(const float4*)(Wp + (size_t)(k0 + 16 + bk) * N + bn);
            pb1 = *(const float4*)(Wp + (size_t)(k0 + 16 + bk + 8) * N + bn);
        }

#pragma unroll
        for (int k = 0; k < 16; k++) {
            float4 a0 = *(const float4*)&As[k][ty * 8];
            float4 a1 = *(const float4*)&As[k][ty * 8 + 4];
            float4 b0 = *(const float4*)&Bs[k][tx * 8];
            float4 b1 = *(const float4*)&Bs[k][tx * 8 + 4];
            float av[8] = {a0.x, a0.y, a0.z, a0.w, a1.x, a1.y, a1.z, a1.w};
            float bv[8] = {b0.x, b0.y, b0.z, b0.w, b1.x, b1.y, b1.z, b1.w};
#pragma unroll
            for (int i = 0; i < 8; i++)
#pragma unroll
                for (int j = 0; j < 8; j++)
                    acc[i][j] += av[i] * bv[j];
        }
        __syncthreads();
    }

#pragma unroll
    for (int i = 0; i < 8; i++) {
        const size_t row = (size_t)(block_m + ty * 8 + i);
        float4 c0 = make_float4(acc[i][0], acc[i][1], acc[i][2], acc[i][3]);
        float4 c1 = make_float4(acc[i][4], acc[i][5], acc[i][6], acc[i][7]);
        *(float4*)(C + row * N + block_n + tx * 8) = c0;
        *(float4*)(C + row * N + block_n + tx * 8 + 4) = c1;
    }
}

// ---------------------------------------------------------------------------
// Causal flash attention over g_qkv (layout [b, s, {q|k|v} interleaved 3*1024]).
// Block = (q-tile of 64 rows) x (b,h). 8 warps, each owns 8 query rows.
// Online softmax; PV via register P + shuffle broadcast.
// Writes attention output in [b, s, h*64+d] layout (head-concat) to g_attn.
// ---------------------------------------------------------------------------
__global__ void __launch_bounds__(256, 3)
attn_kernel(const float* __restrict__ qkv, float* __restrict__ out) {
    __shared__ float Qs[64][64];
    __shared__ float Ks[64][64];   // XOR-swizzled 16B chunks
    __shared__ float Vs[64][64];

    const int t = threadIdx.x;
    const int warp = t / 32;
    const int lane = t % 32;
    const int qtile = blockIdx.x;
    const int b = blockIdx.y / HH;
    const int h = blockIdx.y % HH;

    const float* base = qkv + (size_t)b * SS * (3 * DD) + h * DH;
    const float* Qg = base;             // + s*3072
    const float* Kg = base + DD;
    const float* Vg = base + 2 * DD;

    // load Q tile
    {
        const int r = t / 16;
        const int c4 = (t % 16) * 4;
#pragma unroll
        for (int rr = 0; rr < 64; rr += 16) {
            float4 v = *(const float4*)(Qg + (size_t)(qtile * 64 + r + rr) * (3 * DD) + c4);
            *(float4*)&Qs[r + rr][c4] = v;
        }
    }

    const int r0 = warp * 8;
    const int m0 = lane;
    const int m1 = lane + 32;
    float m_i[8], l_i[8], o0[8], o1[8];
#pragma unroll
    for (int r = 0; r < 8; r++) { m_i[r] = -1e30f; l_i[r] = 0.f; o0[r] = 0.f; o1[r] = 0.f; }

    for (int j = 0; j <= qtile; j++) {
        __syncthreads();   // previous tile consumed (also covers Qs write on j==0)
        {
            const int r = t / 16;
            const int c4 = (t % 16) * 4;
#pragma unroll
            for (int rr = 0; rr < 64; rr += 16) {
                const int row = r + rr;
                float4 kv = *(const float4*)(Kg + (size_t)(j * 64 + row) * (3 * DD) + c4);
                float4 vv = *(const float4*)(Vg + (size_t)(j * 64 + row) * (3 * DD) + c4);
                const int chunk = (c4 >> 2) ^ (row & 15);
                *(float4*)&Ks[row][chunk * 4] = kv;
                *(float4*)&Vs[row][c4] = vv;
            }
        }
        __syncthreads();

        // scores: s0 = Q[r]·K[m0], s1 = Q[r]·K[m1]
        float s0[8], s1[8];
#pragma unroll
        for (int r = 0; r < 8; r++) { s0[r] = 0.f; s1[r] = 0.f; }
#pragma unroll
        for (int d4 = 0; d4 < 16; d4++) {
            float4 k0 = *(const float4*)&Ks[m0][(d4 ^ (m0 & 15)) * 4];
            float4 k1 = *(const float4*)&Ks[m1][(d4 ^ (m1 & 15)) * 4];
#pragma unroll
            for (int r = 0; r < 8; r++) {
                float4 q = *(const float4*)&Qs[r0 + r][d4 * 4];
                s0[r] += q.x * k0.x + q.y * k0.y + q.z * k0.z + q.w * k0.w;
                s1[r] += q.x * k1.x + q.y * k1.y + q.z * k1.z + q.w * k1.w;
            }
        }

        const float scale = 0.125f;   // 1/sqrt(64)
        const bool diag = (j == qtile);
#pragma unroll
        for (int r = 0; r < 8; r++) {
            const int rg = qtile * 64 + r0 + r;
            float sv0 = s0[r] * scale;
            float sv1 = s1[r] * scale;
            if (diag) {
                if (j * 64 + m0 > rg) sv0 = -1e30f;
                if (j * 64 + m1 > rg) sv1 = -1e30f;
            }
            float tmax = fmaxf(sv0, sv1);
#pragma unroll
            for (int off = 16; off > 0; off >>= 1)
                tmax = fmaxf(tmax, __shfl_xor_sync(0xffffffffu, tmax, off));
            const float mnew = fmaxf(m_i[r], tmax);
            const float corr = __expf(m_i[r] - mnew);
            m_i[r] = mnew;
            const float p0 = __expf(sv0 - mnew);
            const float p1 = __expf(sv1 - mnew);
            float psum = p0 + p1;
#pragma unroll
            for (int off = 16; off > 0; off >>= 1)
                psum += __shfl_xor_sync(0xffffffffu, psum, off);
            l_i[r] = l_i[r] * corr + psum;
            o0[r] *= corr;
            o1[r] *= corr;
            s0[r] = p0;   // reuse as P
            s1[r] = p1;
        }

        // PV: O[r][2*lane..+1] += sum_m P[r][m] * V[m][2*lane..+1]
        const int dcol = 2 * lane;
#pragma unroll
        for (int m = 0; m < 32; m++) {
            float2 v0 = *(const float2*)&Vs[m][dcol];
            float2 v1 = *(const float2*)&Vs[m + 32][dcol];
#pragma unroll
            for (int r = 0; r < 8; r++) {
                const float pa = __shfl_sync(0xffffffffu, s0[r], m);
                const float pb = __shfl_sync(0xffffffffu, s1[r], m);
                o0[r] += pa * v0.x + pb * v1.x;
                o1[r] += pa * v0.y + pb * v1.y;
            }
        }
    }

#pragma unroll
    for (int r = 0; r < 8; r++) {
        const float inv = 1.f / l_i[r];
        const int rg = qtile * 64 + r0 + r;
        float2 res = make_float2(o0[r] * inv, o1[r] * inv);
        *(float2*)(out + ((size_t)b * SS + rg) * DD + h * DH + 2 * lane) = res;
    }
}

// ---------------------------------------------------------------------------
extern "C" void kernel_launch(void* const* d_in, const int* in_sizes, int n_in,
                              void* d_out, int out_size) {
    const float* x     = (const float*)d_in[0];   // [8,1024,1024]
    // d_in[1] = mask (bool causal, known statically -> unused)
    const float* w_qkv = (const float*)d_in[2];   // [1024,3072]
    const float* w_out = (const float*)d_in[3];   // [1024,1024]
    float* out = (float*)d_out;                   // [8,1024,1024]

    float* qkv_buf = nullptr;
    float* attn_buf = nullptr;
    cudaGetSymbolAddress((void**)&qkv_buf, g_qkv);
    cudaGetSymbolAddress((void**)&attn_buf, g_attn);

    // 1) QKV projection: [8192,3072] = [8192,1024] @ [1024,3072]
    {
        dim3 grid(3072 / 128, 8192 / 128);
        gemm_kernel<<<grid, 256>>>(x, w_qkv, qkv_buf, 8192, 3072, 1024);
    }
    // 2) causal attention
    {
        dim3 grid(SS / 64, BB * HH);
        attn_kernel<<<grid, 256>>>(qkv_buf, attn_buf);
    }
    // 3) output projection: [8192,1024] = [8192,1024] @ [1024,1024]
    {
        dim3 grid(1024 / 128, 8192 / 128);
        gemm_kernel<<<grid, 256>>>(attn_buf, w_out, out, 8192, 1024, 1024);
    }
}